// round 13
// baseline (speedup 1.0000x reference)
#include <cuda_runtime.h>
#include <cuda_bf16.h>
#include <cstdint>

// ---------------------------------------------------------------------------
// StackedBidirectionalLSTMEncoder  (B=64, T=256, V=128, E=512, U=512)
// Round 13: transposed HMMA scan.
//   z^T[32,64] = UrT[32,512] @ h^T : A = Ur slice STATIC (fragment-major smem,
//   1 LDS.128/frag), B = h natural layout staged via cp.async from global
//   bf16 hi/lo planes (written by epilogue). Register-local LSTM epilogue
//   (no zex exchange). k split in halves to overlap staging with HMMA.
//   embW gather + warp-mma layer-2 GEMM unchanged (validated).
// ---------------------------------------------------------------------------

#define kB 64
#define kT 256
#define kE 512
#define kU 512
#define kG 2048   /* 4U */
#define kF 1024   /* 2U */

// ------------------------------ scratch ------------------------------------
__device__ float g_zx0[33554432];                   // [t*B+b][2048] fwd (layer2)
__device__ float g_zx1[33554432];                   // bwd
__device__ __nv_bfloat16 g_ah[16777216];            // A hi  [16384][1024]
__device__ __nv_bfloat16 g_al[16777216];            // A lo
__device__ __nv_bfloat16 g_bh0[2097152];            // W2f^T hi [2048][1024]
__device__ __nv_bfloat16 g_bl0[2097152];
__device__ __nv_bfloat16 g_bh1[2097152];            // W2b^T hi
__device__ __nv_bfloat16 g_bl1[2097152];
__device__ float g_embw0[262144];                   // emb@W1f+b1f [128][2048]
__device__ float g_embw1[262144];
__device__ __nv_bfloat16 g_hh[2][2][2][kB * kU];    // [layer][dir][par] h hi
__device__ __nv_bfloat16 g_hl[2][2][2][kB * kU];    // h lo
__device__ unsigned int g_bar[4];                   // [layer*2+dir]

// ------------------------------ f32x2 helpers ------------------------------
__device__ __forceinline__ unsigned long long pk2(float lo, float hi) {
    unsigned long long r;
    asm("mov.b64 %0, {%1, %2};" : "=l"(r) : "f"(lo), "f"(hi));
    return r;
}
__device__ __forceinline__ void upk2(unsigned long long v, float& lo, float& hi) {
    asm("mov.b64 {%0, %1}, %2;" : "=f"(lo), "=f"(hi) : "l"(v));
}
__device__ __forceinline__ unsigned long long ffma2(unsigned long long a,
                                                    unsigned long long b,
                                                    unsigned long long c) {
    unsigned long long d;
    asm("fma.rn.f32x2 %0, %1, %2, %3;" : "=l"(d) : "l"(a), "l"(b), "l"(c));
    return d;
}
__device__ __forceinline__ float sigmoidf_(float x) {
    return 1.0f / (1.0f + __expf(-x));
}
__device__ __forceinline__ uint32_t pack_bf16x2(__nv_bfloat16 a, __nv_bfloat16 b) {
    unsigned short ua = *reinterpret_cast<unsigned short*>(&a);
    unsigned short ub = *reinterpret_cast<unsigned short*>(&b);
    return (uint32_t)ua | ((uint32_t)ub << 16);
}

// ------------------------------ cp.async helpers ----------------------------
__device__ __forceinline__ uint32_t smem_u32(const void* p) {
    uint32_t a;
    asm("{ .reg .u64 t; cvta.to.shared.u64 t, %1; cvt.u32.u64 %0, t; }"
        : "=r"(a) : "l"(p));
    return a;
}
__device__ __forceinline__ void cp16(uint32_t d, const void* s) {
    asm volatile("cp.async.cg.shared.global [%0], [%1], 16;" :: "r"(d), "l"(s));
}
__device__ __forceinline__ void cp_commit() { asm volatile("cp.async.commit_group;" ::: "memory"); }
__device__ __forceinline__ void cp_wait1()  { asm volatile("cp.async.wait_group 1;" ::: "memory"); }
__device__ __forceinline__ void cp_wait0()  { asm volatile("cp.async.wait_group 0;" ::: "memory"); }

// bf16 warp mma: D(16x8,f32) += A(16x16 row) * B(16x8 col)
__device__ __forceinline__ void mma16816(float* c, const uint32_t* a,
                                         const uint32_t* b) {
    asm volatile(
        "mma.sync.aligned.m16n8k16.row.col.f32.bf16.bf16.f32 "
        "{%0,%1,%2,%3}, {%4,%5,%6,%7}, {%8,%9}, {%0,%1,%2,%3};"
        : "+f"(c[0]), "+f"(c[1]), "+f"(c[2]), "+f"(c[3])
        : "r"(a[0]), "r"(a[1]), "r"(a[2]), "r"(a[3]), "r"(b[0]), "r"(b[1]));
}

// ------------------------------ init ----------------------------------------
__global__ void init_kernel() {
    int i = blockIdx.x * blockDim.x + threadIdx.x;
    if (i < 4) g_bar[i] = 0u;
    uint32_t* h0 = (uint32_t*)g_hh;
    uint32_t* h1 = (uint32_t*)g_hl;
    for (int j = i; j < 2 * 2 * 2 * kB * kU / 2; j += gridDim.x * blockDim.x) {
        h0[j] = 0u;
        h1[j] = 0u;
    }
}

// ------------------------------ fp32 GEMM (embW only; M=128) ---------------
__global__ __launch_bounds__(256, 2) void gemm_f32(
    const float* __restrict__ A, const float* __restrict__ W,
    const float* __restrict__ bias, int c_sel, int K) {
    float* __restrict__ C = c_sel ? g_embw1 : g_embw0;
    __shared__ float As[16][136];
    __shared__ float Bs[16][128];
    const int tid = threadIdx.x;
    const int tx = tid & 15;
    const int ty = tid >> 4;
    const int m0 = blockIdx.y * 128;
    const int n0 = blockIdx.x * 128;

    unsigned long long acc[8][4];
#pragma unroll
    for (int i = 0; i < 8; i++)
#pragma unroll
        for (int j = 0; j < 4; j++) acc[i][j] = pk2(0.0f, 0.0f);

    for (int k0 = 0; k0 < K; k0 += 16) {
#pragma unroll
        for (int l = 0; l < 2; ++l) {
            int f = tid + l * 256;
            int m = f >> 2, kc = (f & 3) * 4;
            float4 v = *(const float4*)(A + (size_t)(m0 + m) * K + k0 + kc);
            As[kc + 0][m] = v.x; As[kc + 1][m] = v.y;
            As[kc + 2][m] = v.z; As[kc + 3][m] = v.w;
            int kr = f >> 5, nc = (f & 31) * 4;
            *(float4*)&Bs[kr][nc] =
                *(const float4*)(W + (size_t)(k0 + kr) * kG + n0 + nc);
        }
        __syncthreads();
#pragma unroll
        for (int k = 0; k < 16; ++k) {
            float4 a0 = *(const float4*)&As[k][ty * 8];
            float4 a1 = *(const float4*)&As[k][ty * 8 + 4];
            float4 b0 = *(const float4*)&Bs[k][tx * 8];
            float4 b1 = *(const float4*)&Bs[k][tx * 8 + 4];
            unsigned long long bp[4] = {pk2(b0.x, b0.y), pk2(b0.z, b0.w),
                                        pk2(b1.x, b1.y), pk2(b1.z, b1.w)};
            float av[8] = {a0.x, a0.y, a0.z, a0.w, a1.x, a1.y, a1.z, a1.w};
#pragma unroll
            for (int i = 0; i < 8; i++) {
                unsigned long long ad = pk2(av[i], av[i]);
#pragma unroll
                for (int j = 0; j < 4; j++) acc[i][j] = ffma2(ad, bp[j], acc[i][j]);
            }
        }
        __syncthreads();
    }
#pragma unroll
    for (int i = 0; i < 8; i++) {
        int m = m0 + ty * 8 + i;
#pragma unroll
        for (int jh = 0; jh < 2; jh++) {
            float l0, h0, l1, h1;
            upk2(acc[i][jh * 2 + 0], l0, h0);
            upk2(acc[i][jh * 2 + 1], l1, h1);
            int n = n0 + tx * 8 + jh * 4;
            float4 v;
            v.x = l0 + bias[n + 0];
            v.y = h0 + bias[n + 1];
            v.z = l1 + bias[n + 2];
            v.w = h1 + bias[n + 3];
            *(float4*)(C + (size_t)m * kG + n) = v;
        }
    }
}

// ------------------------------ W2 transpose + bf16 split -------------------
__global__ void wsplit_kernel(const float* __restrict__ W2f,
                              const float* __restrict__ W2b) {
    __shared__ float s[32][33];
    const int d = blockIdx.z;
    const float* __restrict__ W = d ? W2b : W2f;
    __nv_bfloat16* __restrict__ Bh = d ? g_bh1 : g_bh0;
    __nv_bfloat16* __restrict__ Bl = d ? g_bl1 : g_bl0;
    const int n0 = blockIdx.x * 32, k0 = blockIdx.y * 32;
    const int tx = threadIdx.x & 31, ty = threadIdx.x >> 5;
#pragma unroll
    for (int i = 0; i < 4; ++i) {
        int k = ty + i * 8;
        s[k][tx] = W[(size_t)(k0 + k) * kG + n0 + tx];
    }
    __syncthreads();
#pragma unroll
    for (int i = 0; i < 4; ++i) {
        int r = ty + i * 8;
        float v = s[tx][r];
        __nv_bfloat16 hi = __float2bfloat16(v);
        float lo = v - __bfloat162float(hi);
        size_t o = (size_t)(n0 + r) * 1024 + k0 + tx;
        Bh[o] = hi;
        Bl[o] = __float2bfloat16(lo);
    }
}

// ------------------------------ warp-mma layer-2 GEMM (validated) ----------
#define TILE_B   10240
#define STAGE_B  (4 * TILE_B)
#define MM_SMEM  (3 * STAGE_B)

__global__ __launch_bounds__(256, 1) void mma_gemm_kernel(
    const float* __restrict__ bias_f, const float* __restrict__ bias_b) {
    extern __shared__ char dynsmem[];
    const int tid = threadIdx.x;
    const int wid = tid >> 5, lane = tid & 31;
    const int g = lane >> 2, t = lane & 3;
    const int wm = wid & 3, wn = wid >> 2;
    const int d = blockIdx.z;
    const int n0 = blockIdx.x * 128;
    const int m0 = blockIdx.y * 128;
    const __nv_bfloat16* __restrict__ Bh = d ? g_bh1 : g_bh0;
    const __nv_bfloat16* __restrict__ Bl = d ? g_bl1 : g_bl0;
    const float* __restrict__ bias = d ? bias_b : bias_f;
    float* __restrict__ zx = d ? g_zx1 : g_zx0;

    const uint32_t sb32 = smem_u32(dynsmem);

    float acc[2][8][4];
#pragma unroll
    for (int mi = 0; mi < 2; mi++)
#pragma unroll
        for (int ni = 0; ni < 8; ni++)
#pragma unroll
            for (int v = 0; v < 4; v++) acc[mi][ni][v] = 0.0f;

    auto load_chunk = [&](int s, int kc) {
        const uint32_t base = sb32 + (uint32_t)s * STAGE_B;
        const int k0 = kc * 32;
        for (int idx = tid; idx < 2048; idx += 256) {
            int tile = idx >> 9;
            int r = (idx >> 2) & 127;
            int c = idx & 3;
            const __nv_bfloat16* src;
            if (tile < 2) src = (tile == 0 ? g_ah : g_al) + (size_t)(m0 + r) * 1024 + k0 + c * 8;
            else          src = (tile == 2 ? Bh : Bl)     + (size_t)(n0 + r) * 1024 + k0 + c * 8;
            cp16(base + tile * TILE_B + r * 80 + c * 16, src);
        }
        cp_commit();
    };

    load_chunk(0, 0);
    load_chunk(1, 1);

    for (int c = 0; c < 32; ++c) {
        if (c + 1 < 32) cp_wait1(); else cp_wait0();
        __syncthreads();
        if (c + 2 < 32) load_chunk((c + 2) % 3, c + 2);

        const char* stg = dynsmem + (size_t)(c % 3) * STAGE_B;
        const char* pAh = stg;
        const char* pAl = stg + TILE_B;
        const char* pBh = stg + 2 * TILE_B;
        const char* pBl = stg + 3 * TILE_B;

#pragma unroll
        for (int ks = 0; ks < 2; ++ks) {
            const int kb = ks * 16;
            uint32_t ah[2][4], al[2][4];
#pragma unroll
            for (int mi = 0; mi < 2; mi++) {
                int ra = wm * 32 + mi * 16 + g;
                int co = (kb + t * 2) * 2;
                ah[mi][0] = *(const uint32_t*)(pAh + (ra)     * 80 + co);
                ah[mi][1] = *(const uint32_t*)(pAh + (ra + 8) * 80 + co);
                ah[mi][2] = *(const uint32_t*)(pAh + (ra)     * 80 + co + 16);
                ah[mi][3] = *(const uint32_t*)(pAh + (ra + 8) * 80 + co + 16);
                al[mi][0] = *(const uint32_t*)(pAl + (ra)     * 80 + co);
                al[mi][1] = *(const uint32_t*)(pAl + (ra + 8) * 80 + co);
                al[mi][2] = *(const uint32_t*)(pAl + (ra)     * 80 + co + 16);
                al[mi][3] = *(const uint32_t*)(pAl + (ra + 8) * 80 + co + 16);
            }
#pragma unroll
            for (int ni = 0; ni < 8; ni++) {
                int rb = wn * 64 + ni * 8 + g;
                int co = (kb + t * 2) * 2;
                uint32_t bh[2], bl[2];
                bh[0] = *(const uint32_t*)(pBh + rb * 80 + co);
                bh[1] = *(const uint32_t*)(pBh + rb * 80 + co + 16);
                bl[0] = *(const uint32_t*)(pBl + rb * 80 + co);
                bl[1] = *(const uint32_t*)(pBl + rb * 80 + co + 16);
#pragma unroll
                for (int mi = 0; mi < 2; mi++) {
                    mma16816(acc[mi][ni], ah[mi], bh);
                    mma16816(acc[mi][ni], al[mi], bh);
                    mma16816(acc[mi][ni], ah[mi], bl);
                }
            }
        }
        __syncthreads();
    }

#pragma unroll
    for (int mi = 0; mi < 2; mi++) {
        int m = m0 + wm * 32 + mi * 16 + g;
#pragma unroll
        for (int ni = 0; ni < 8; ni++) {
            int n = n0 + wn * 64 + ni * 8 + t * 2;
            float bx = __ldg(bias + n), by = __ldg(bias + n + 1);
            float2 v0 = {acc[mi][ni][0] + bx, acc[mi][ni][1] + by};
            float2 v1 = {acc[mi][ni][2] + bx, acc[mi][ni][3] + by};
            *(float2*)(zx + (size_t)m * kG + n) = v0;
            *(float2*)(zx + (size_t)(m + 8) * kG + n) = v1;
        }
    }
}

// ------------------------------ persistent transposed HMMA scan -------------
// 128 CTAs: CTA = dir*64 + g owns 8 units (32 gate rows of z^T).
// z^T[32,64] = UrT_slice[32,512] @ h^T; A static fragment-major, B = h planes.
#define SC_BSTRIDE 1040
#define SC_PLANE   (64 * SC_BSTRIDE)        /* 66560 */
#define SC_OFF_BH  65536
#define SC_OFF_BL  (SC_OFF_BH + SC_PLANE)   /* 132096 */
#define SCAN_SMEM  (SC_OFF_BL + SC_PLANE)   /* 198656 */

__global__ __launch_bounds__(256, 1) void scan_kernel(
    const float* __restrict__ Ur_f, const float* __restrict__ Ur_b,
    const int* __restrict__ enc,
    float* __restrict__ out2, float* __restrict__ h_final,
    float* __restrict__ c_final, int layer2) {
    extern __shared__ char dynsmem[];
    char* pA  = dynsmem;
    char* pBh = dynsmem + SC_OFF_BH;
    char* pBl = dynsmem + SC_OFF_BL;

    const int cta = blockIdx.x;
    const int d = cta >> 6;
    const int g = cta & 63;
    const int j0 = g * 8;
    const int tid = threadIdx.x;
    const int wid = tid >> 5, lane = tid & 31;
    const int fg = lane >> 2, ft = lane & 3;
    const int n0w = wid * 8;                 // warp batch base
    const int b0 = n0w + ft * 2, b1 = b0 + 1;  // owned batches
    // staging mapping: thread stages one (plane, row, k-half)
    const int spl = tid >> 7;                // 0: hi plane, 1: lo plane
    const int srow = (tid >> 1) & 63;
    const int shalf = tid & 1;               // k-half

    const float* __restrict__ Ur = d ? Ur_b : Ur_f;
    const float* __restrict__ ew = d ? g_embw1 : g_embw0;
    const float* __restrict__ zx = d ? g_zx1 : g_zx0;
    unsigned int* barp = &g_bar[layer2 * 2 + d];

    // -------- A (UrT slice) -> fragment-major smem, hi/lo, once ------------
    // slot i = ks*128 + mi*64 + pl*32 + lane ; 16B per slot (4 frag regs)
    for (int i = tid; i < 4096; i += 256) {
        int ks = i >> 7, rest = i & 127;
        int mi = rest >> 6, pl = (rest >> 5) & 1, ln = rest & 31;
        int lfg = ln >> 2, lft = ln & 3;
        uint32_t regs[4];
#pragma unroll
        for (int r = 0; r < 4; ++r) {
            int m = mi * 16 + lfg + ((r & 1) << 3);
            int kk = ks * 16 + lft * 2 + ((r >> 1) << 3);
            int col = (m >> 3) * kU + j0 + (m & 7);
            float v0 = __ldg(Ur + (size_t)kk * kG + col);
            float v1 = __ldg(Ur + (size_t)(kk + 1) * kG + col);
            __nv_bfloat16 h0 = __float2bfloat16(v0);
            __nv_bfloat16 h1 = __float2bfloat16(v1);
            if (pl == 0) {
                regs[r] = pack_bf16x2(h0, h1);
            } else {
                __nv_bfloat16 l0 = __float2bfloat16(v0 - __bfloat162float(h0));
                __nv_bfloat16 l1 = __float2bfloat16(v1 - __bfloat162float(h1));
                regs[r] = pack_bf16x2(l0, l1);
            }
        }
        *(uint4*)(pA + (size_t)i * 16) = *(uint4*)regs;
    }
    __syncthreads();

    // staging smem dst (constant) and addresses
    const uint32_t sdst = smem_u32(dynsmem) +
        (spl ? SC_OFF_BL : SC_OFF_BH) + srow * SC_BSTRIDE + shalf * 512;

    float hp[2] = {0.f, 0.f}, cp[2] = {0.f, 0.f};

    for (int s = 0; s < kT; ++s) {
        const int t = d ? (kT - 1 - s) : s;
        const int par = s & 1;
        const __nv_bfloat16* __restrict__ ihh = g_hh[layer2][d][par];
        const __nv_bfloat16* __restrict__ ihl = g_hl[layer2][d][par];
        __nv_bfloat16* __restrict__ ohh = g_hh[layer2][d][par ^ 1];
        __nv_bfloat16* __restrict__ ohl = g_hl[layer2][d][par ^ 1];

        // zx prefetch for owned cells (b0, fg), (b1, fg)
        const int tokA = __ldg(enc + b0 * kT + t);
        const int tokB = __ldg(enc + b1 * kT + t);
        float zr[2][4];
        if (!layer2) {
#pragma unroll
            for (int q = 0; q < 4; q++) {
                zr[0][q] = __ldg(ew + (size_t)tokA * kG + q * kU + j0 + fg);
                zr[1][q] = __ldg(ew + (size_t)tokB * kG + q * kU + j0 + fg);
            }
        } else {
#pragma unroll
            for (int q = 0; q < 4; q++) {
                zr[0][q] = __ldg(zx + ((size_t)t * kB + b0) * kG + q * kU + j0 + fg);
                zr[1][q] = __ldg(zx + ((size_t)t * kB + b1) * kG + q * kU + j0 + fg);
            }
        }

        // ---- stage B (h planes) via cp.async; group0 = k-half 0 -----------
        const __nv_bfloat16* ssrc =
            (spl ? ihl : ihh) + srow * kU + shalf * 256;
        if (shalf == 0) {
#pragma unroll
            for (int c = 0; c < 32; ++c) cp16(sdst + c * 16, ssrc + c * 8);
        }
        cp_commit();
        if (shalf == 1) {
#pragma unroll
            for (int c = 0; c < 32; ++c) cp16(sdst + c * 16, ssrc + c * 8);
        }
        cp_commit();

        float acc[2][4] = {{0.f, 0.f, 0.f, 0.f}, {0.f, 0.f, 0.f, 0.f}};
        const char* brh = pBh + (n0w + fg) * SC_BSTRIDE;
        const char* brl = pBl + (n0w + fg) * SC_BSTRIDE;

#pragma unroll
        for (int half = 0; half < 2; ++half) {
            if (half == 0) cp_wait1(); else cp_wait0();
            __syncthreads();
#pragma unroll
            for (int ks = half * 16; ks < half * 16 + 16; ++ks) {
                const int co = (ks * 16 + ft * 2) * 2;
                uint32_t bh[2], bl[2];
                bh[0] = *(const uint32_t*)(brh + co);
                bh[1] = *(const uint32_t*)(brh + co + 16);
                bl[0] = *(const uint32_t*)(brl + co);
                bl[1] = *(const uint32_t*)(brl + co + 16);
#pragma unroll
                for (int mi = 0; mi < 2; ++mi) {
                    uint4 ah = *(const uint4*)(pA + ((ks * 4 + mi * 2) * 512) + lane * 16);
                    uint4 al = *(const uint4*)(pA + ((ks * 4 + mi * 2 + 1) * 512) + lane * 16);
                    mma16816(acc[mi], (const uint32_t*)&ah, bh);
                    mma16816(acc[mi], (const uint32_t*)&al, bh);
                    mma16816(acc[mi], (const uint32_t*)&ah, bl);
                }
            }
        }

        // ---- register-local LSTM epilogue ---------------------------------
#pragma unroll
        for (int c = 0; c < 2; ++c) {
            const int b = c ? b1 : b0;
            const int msk = c ? (tokB != 0) : (tokA != 0);
            float zi = acc[0][c]     + zr[c][0];
            float zf = acc[0][2 + c] + zr[c][1];
            float zg = acc[1][c]     + zr[c][2];
            float zo = acc[1][2 + c] + zr[c][3];
            float ii = sigmoidf_(zi), ff = sigmoidf_(zf);
            float gg = tanhf(zg), oo = sigmoidf_(zo);
            float cn = ff * cp[c] + ii * gg;
            float hn = oo * tanhf(cn);
            if (!msk) { hn = hp[c]; cn = cp[c]; }
            hp[c] = hn; cp[c] = cn;
            __nv_bfloat16 bhi = __float2bfloat16(hn);
            __nv_bfloat16 blo = __float2bfloat16(hn - __bfloat162float(bhi));
            ohh[b * kU + j0 + fg] = bhi;
            ohl[b * kU + j0 + fg] = blo;
            if (!layer2) {
                size_t idx = ((size_t)t * kB + b) * kF + d * kU + j0 + fg;
                g_ah[idx] = bhi;
                g_al[idx] = blo;
            } else {
                out2[((size_t)b * kT + t) * kF + d * kU + j0 + fg] = hn;
                if (s == kT - 1) {
                    h_final[b * kF + d * kU + j0 + fg] = hn;
                    c_final[b * kF + d * kU + j0 + fg] = cn;
                }
            }
        }

        // ---- inter-CTA barrier (per layer+direction group) ----------------
        if (s != kT - 1) {
            __threadfence();
            __syncthreads();
            if (tid == 0) {
                unsigned tgt = 64u * (unsigned)(s + 1);
                atomicAdd(barp, 1u);
                unsigned v;
                do {
                    asm volatile("ld.global.cg.u32 %0, [%1];"
                                 : "=r"(v) : "l"(barp) : "memory");
                    if (v < tgt) __nanosleep(32);
                } while (v < tgt);
                __threadfence();
            }
            __syncthreads();
        }
    }
}

// ------------------------------ launch --------------------------------------
extern "C" void kernel_launch(void* const* d_in, const int* in_sizes, int n_in,
                              void* d_out, int out_size) {
    const int*   enc = (const int*)d_in[0];
    const float* emb = (const float*)d_in[1];
    const float* W1f = (const float*)d_in[2];
    const float* U1f = (const float*)d_in[3];
    const float* b1f = (const float*)d_in[4];
    const float* W1b = (const float*)d_in[5];
    const float* U1b = (const float*)d_in[6];
    const float* b1b = (const float*)d_in[7];
    const float* W2f = (const float*)d_in[8];
    const float* U2f = (const float*)d_in[9];
    const float* b2f = (const float*)d_in[10];
    const float* W2b = (const float*)d_in[11];
    const float* U2b = (const float*)d_in[12];
    const float* b2b = (const float*)d_in[13];

    float* out  = (float*)d_out;
    float* out2 = out;                                   // [B,T,2U]
    float* h2   = out + (size_t)kB * kT * kF;
    float* c2   = h2 + (size_t)kB * kF;

    cudaFuncSetAttribute(scan_kernel, cudaFuncAttributeMaxDynamicSharedMemorySize,
                         SCAN_SMEM);
    cudaFuncSetAttribute(mma_gemm_kernel, cudaFuncAttributeMaxDynamicSharedMemorySize,
                         MM_SMEM);

    // embW = emb @ W1 + b1  (V=128 -> gather replaces layer-1 GEMM)
    gemm_f32<<<dim3(16, 1), 256>>>(emb, W1f, b1f, 0, kE);
    gemm_f32<<<dim3(16, 1), 256>>>(emb, W1b, b1b, 1, kE);

    // W2 transpose + bf16 hi/lo split
    wsplit_kernel<<<dim3(64, 32, 2), 256>>>(W2f, W2b);

    // zero h planes + barrier counters
    init_kernel<<<128, 256>>>();

    // layer-1 scan (transposed HMMA; emits bf16 hi/lo A operand)
    scan_kernel<<<128, 256, SCAN_SMEM>>>(U1f, U1b, enc,
                                         nullptr, nullptr, nullptr, 0);

    // layer-2 input projection: warp-mma bf16, 3-pass split, cp.async pipeline
    mma_gemm_kernel<<<dim3(16, 128, 2), 256, MM_SMEM>>>(b2f, b2b);

    // layer-2 scan -> outputs
    scan_kernel<<<128, 256, SCAN_SMEM>>>(U2f, U2b, enc,
                                         out2, h2, c2, 1);
}

// round 14
// speedup vs baseline: 1.0471x; 1.0471x over previous
#include <cuda_runtime.h>
#include <cuda_bf16.h>
#include <cstdint>

// ---------------------------------------------------------------------------
// StackedBidirectionalLSTMEncoder  (B=64, T=256, V=128, E=512, U=512)
// Round 14: overhead attack.
//   scan: release/acquire barrier (no threadfence/nanosleep), single staging
//         group + single HMMA sweep, epilogue store reorder.
//   mma_gemm: 2-stage pipeline, occupancy 2.
//   embW gather + everything else unchanged (validated).
// ---------------------------------------------------------------------------

#define kB 64
#define kT 256
#define kE 512
#define kU 512
#define kG 2048   /* 4U */
#define kF 1024   /* 2U */

// ------------------------------ scratch ------------------------------------
__device__ float g_zx0[33554432];                   // [t*B+b][2048] fwd (layer2)
__device__ float g_zx1[33554432];                   // bwd
__device__ __nv_bfloat16 g_ah[16777216];            // A hi  [16384][1024]
__device__ __nv_bfloat16 g_al[16777216];            // A lo
__device__ __nv_bfloat16 g_bh0[2097152];            // W2f^T hi [2048][1024]
__device__ __nv_bfloat16 g_bl0[2097152];
__device__ __nv_bfloat16 g_bh1[2097152];            // W2b^T hi
__device__ __nv_bfloat16 g_bl1[2097152];
__device__ float g_embw0[262144];                   // emb@W1f+b1f [128][2048]
__device__ float g_embw1[262144];
__device__ __nv_bfloat16 g_hh[2][2][2][kB * kU];    // [layer][dir][par] h hi
__device__ __nv_bfloat16 g_hl[2][2][2][kB * kU];    // h lo
__device__ unsigned int g_bar[4];                   // [layer*2+dir]

// ------------------------------ f32x2 helpers ------------------------------
__device__ __forceinline__ unsigned long long pk2(float lo, float hi) {
    unsigned long long r;
    asm("mov.b64 %0, {%1, %2};" : "=l"(r) : "f"(lo), "f"(hi));
    return r;
}
__device__ __forceinline__ void upk2(unsigned long long v, float& lo, float& hi) {
    asm("mov.b64 {%0, %1}, %2;" : "=f"(lo), "=f"(hi) : "l"(v));
}
__device__ __forceinline__ unsigned long long ffma2(unsigned long long a,
                                                    unsigned long long b,
                                                    unsigned long long c) {
    unsigned long long d;
    asm("fma.rn.f32x2 %0, %1, %2, %3;" : "=l"(d) : "l"(a), "l"(b), "l"(c));
    return d;
}
__device__ __forceinline__ float sigmoidf_(float x) {
    return 1.0f / (1.0f + __expf(-x));
}
__device__ __forceinline__ uint32_t pack_bf16x2(__nv_bfloat16 a, __nv_bfloat16 b) {
    unsigned short ua = *reinterpret_cast<unsigned short*>(&a);
    unsigned short ub = *reinterpret_cast<unsigned short*>(&b);
    return (uint32_t)ua | ((uint32_t)ub << 16);
}

// ------------------------------ cp.async helpers ----------------------------
__device__ __forceinline__ uint32_t smem_u32(const void* p) {
    uint32_t a;
    asm("{ .reg .u64 t; cvta.to.shared.u64 t, %1; cvt.u32.u64 %0, t; }"
        : "=r"(a) : "l"(p));
    return a;
}
__device__ __forceinline__ void cp16(uint32_t d, const void* s) {
    asm volatile("cp.async.cg.shared.global [%0], [%1], 16;" :: "r"(d), "l"(s));
}
__device__ __forceinline__ void cp_commit() { asm volatile("cp.async.commit_group;" ::: "memory"); }
__device__ __forceinline__ void cp_wait1()  { asm volatile("cp.async.wait_group 1;" ::: "memory"); }
__device__ __forceinline__ void cp_wait0()  { asm volatile("cp.async.wait_group 0;" ::: "memory"); }

// release/acquire barrier primitives (gpu scope)
__device__ __forceinline__ void bar_arrive_release(unsigned int* p) {
    asm volatile("red.release.gpu.global.add.u32 [%0], %1;"
                 :: "l"(p), "r"(1u) : "memory");
}
__device__ __forceinline__ unsigned int bar_poll_acquire(unsigned int* p) {
    unsigned int v;
    asm volatile("ld.acquire.gpu.global.u32 %0, [%1];"
                 : "=r"(v) : "l"(p) : "memory");
    return v;
}

// bf16 warp mma: D(16x8,f32) += A(16x16 row) * B(16x8 col)
__device__ __forceinline__ void mma16816(float* c, const uint32_t* a,
                                         const uint32_t* b) {
    asm volatile(
        "mma.sync.aligned.m16n8k16.row.col.f32.bf16.bf16.f32 "
        "{%0,%1,%2,%3}, {%4,%5,%6,%7}, {%8,%9}, {%0,%1,%2,%3};"
        : "+f"(c[0]), "+f"(c[1]), "+f"(c[2]), "+f"(c[3])
        : "r"(a[0]), "r"(a[1]), "r"(a[2]), "r"(a[3]), "r"(b[0]), "r"(b[1]));
}

// ------------------------------ init ----------------------------------------
__global__ void init_kernel() {
    int i = blockIdx.x * blockDim.x + threadIdx.x;
    if (i < 4) g_bar[i] = 0u;
    uint32_t* h0 = (uint32_t*)g_hh;
    uint32_t* h1 = (uint32_t*)g_hl;
    for (int j = i; j < 2 * 2 * 2 * kB * kU / 2; j += gridDim.x * blockDim.x) {
        h0[j] = 0u;
        h1[j] = 0u;
    }
}

// ------------------------------ fp32 GEMM (embW only; M=128) ---------------
__global__ __launch_bounds__(256, 2) void gemm_f32(
    const float* __restrict__ A, const float* __restrict__ W,
    const float* __restrict__ bias, int c_sel, int K) {
    float* __restrict__ C = c_sel ? g_embw1 : g_embw0;
    __shared__ float As[16][136];
    __shared__ float Bs[16][128];
    const int tid = threadIdx.x;
    const int tx = tid & 15;
    const int ty = tid >> 4;
    const int m0 = blockIdx.y * 128;
    const int n0 = blockIdx.x * 128;

    unsigned long long acc[8][4];
#pragma unroll
    for (int i = 0; i < 8; i++)
#pragma unroll
        for (int j = 0; j < 4; j++) acc[i][j] = pk2(0.0f, 0.0f);

    for (int k0 = 0; k0 < K; k0 += 16) {
#pragma unroll
        for (int l = 0; l < 2; ++l) {
            int f = tid + l * 256;
            int m = f >> 2, kc = (f & 3) * 4;
            float4 v = *(const float4*)(A + (size_t)(m0 + m) * K + k0 + kc);
            As[kc + 0][m] = v.x; As[kc + 1][m] = v.y;
            As[kc + 2][m] = v.z; As[kc + 3][m] = v.w;
            int kr = f >> 5, nc = (f & 31) * 4;
            *(float4*)&Bs[kr][nc] =
                *(const float4*)(W + (size_t)(k0 + kr) * kG + n0 + nc);
        }
        __syncthreads();
#pragma unroll
        for (int k = 0; k < 16; ++k) {
            float4 a0 = *(const float4*)&As[k][ty * 8];
            float4 a1 = *(const float4*)&As[k][ty * 8 + 4];
            float4 b0 = *(const float4*)&Bs[k][tx * 8];
            float4 b1 = *(const float4*)&Bs[k][tx * 8 + 4];
            unsigned long long bp[4] = {pk2(b0.x, b0.y), pk2(b0.z, b0.w),
                                        pk2(b1.x, b1.y), pk2(b1.z, b1.w)};
            float av[8] = {a0.x, a0.y, a0.z, a0.w, a1.x, a1.y, a1.z, a1.w};
#pragma unroll
            for (int i = 0; i < 8; i++) {
                unsigned long long ad = pk2(av[i], av[i]);
#pragma unroll
                for (int j = 0; j < 4; j++) acc[i][j] = ffma2(ad, bp[j], acc[i][j]);
            }
        }
        __syncthreads();
    }
#pragma unroll
    for (int i = 0; i < 8; i++) {
        int m = m0 + ty * 8 + i;
#pragma unroll
        for (int jh = 0; jh < 2; jh++) {
            float l0, h0, l1, h1;
            upk2(acc[i][jh * 2 + 0], l0, h0);
            upk2(acc[i][jh * 2 + 1], l1, h1);
            int n = n0 + tx * 8 + jh * 4;
            float4 v;
            v.x = l0 + bias[n + 0];
            v.y = h0 + bias[n + 1];
            v.z = l1 + bias[n + 2];
            v.w = h1 + bias[n + 3];
            *(float4*)(C + (size_t)m * kG + n) = v;
        }
    }
}

// ------------------------------ W2 transpose + bf16 split -------------------
__global__ void wsplit_kernel(const float* __restrict__ W2f,
                              const float* __restrict__ W2b) {
    __shared__ float s[32][33];
    const int d = blockIdx.z;
    const float* __restrict__ W = d ? W2b : W2f;
    __nv_bfloat16* __restrict__ Bh = d ? g_bh1 : g_bh0;
    __nv_bfloat16* __restrict__ Bl = d ? g_bl1 : g_bl0;
    const int n0 = blockIdx.x * 32, k0 = blockIdx.y * 32;
    const int tx = threadIdx.x & 31, ty = threadIdx.x >> 5;
#pragma unroll
    for (int i = 0; i < 4; ++i) {
        int k = ty + i * 8;
        s[k][tx] = W[(size_t)(k0 + k) * kG + n0 + tx];
    }
    __syncthreads();
#pragma unroll
    for (int i = 0; i < 4; ++i) {
        int r = ty + i * 8;
        float v = s[tx][r];
        __nv_bfloat16 hi = __float2bfloat16(v);
        float lo = v - __bfloat162float(hi);
        size_t o = (size_t)(n0 + r) * 1024 + k0 + tx;
        Bh[o] = hi;
        Bl[o] = __float2bfloat16(lo);
    }
}

// ------------------------------ warp-mma layer-2 GEMM -----------------------
// 2-stage pipeline, occupancy 2 (80KB smem / CTA).
#define TILE_B   10240
#define STAGE_B  (4 * TILE_B)
#define MM_SMEM  (2 * STAGE_B)

__global__ __launch_bounds__(256, 2) void mma_gemm_kernel(
    const float* __restrict__ bias_f, const float* __restrict__ bias_b) {
    extern __shared__ char dynsmem[];
    const int tid = threadIdx.x;
    const int wid = tid >> 5, lane = tid & 31;
    const int g = lane >> 2, t = lane & 3;
    const int wm = wid & 3, wn = wid >> 2;
    const int d = blockIdx.z;
    const int n0 = blockIdx.x * 128;
    const int m0 = blockIdx.y * 128;
    const __nv_bfloat16* __restrict__ Bh = d ? g_bh1 : g_bh0;
    const __nv_bfloat16* __restrict__ Bl = d ? g_bl1 : g_bl0;
    const float* __restrict__ bias = d ? bias_b : bias_f;
    float* __restrict__ zx = d ? g_zx1 : g_zx0;

    const uint32_t sb32 = smem_u32(dynsmem);

    float acc[2][8][4];
#pragma unroll
    for (int mi = 0; mi < 2; mi++)
#pragma unroll
        for (int ni = 0; ni < 8; ni++)
#pragma unroll
            for (int v = 0; v < 4; v++) acc[mi][ni][v] = 0.0f;

    auto load_chunk = [&](int s, int kc) {
        const uint32_t base = sb32 + (uint32_t)s * STAGE_B;
        const int k0 = kc * 32;
        for (int idx = tid; idx < 2048; idx += 256) {
            int tile = idx >> 9;
            int r = (idx >> 2) & 127;
            int c = idx & 3;
            const __nv_bfloat16* src;
            if (tile < 2) src = (tile == 0 ? g_ah : g_al) + (size_t)(m0 + r) * 1024 + k0 + c * 8;
            else          src = (tile == 2 ? Bh : Bl)     + (size_t)(n0 + r) * 1024 + k0 + c * 8;
            cp16(base + tile * TILE_B + r * 80 + c * 16, src);
        }
        cp_commit();
    };

    load_chunk(0, 0);
    load_chunk(1, 1);

    for (int c = 0; c < 32; ++c) {
        if (c + 1 < 32) cp_wait1(); else cp_wait0();
        __syncthreads();

        const char* stg = dynsmem + (size_t)(c & 1) * STAGE_B;
        const char* pAh = stg;
        const char* pAl = stg + TILE_B;
        const char* pBh = stg + 2 * TILE_B;
        const char* pBl = stg + 3 * TILE_B;

#pragma unroll
        for (int ks = 0; ks < 2; ++ks) {
            const int kb = ks * 16;
            uint32_t ah[2][4], al[2][4];
#pragma unroll
            for (int mi = 0; mi < 2; mi++) {
                int ra = wm * 32 + mi * 16 + g;
                int co = (kb + t * 2) * 2;
                ah[mi][0] = *(const uint32_t*)(pAh + (ra)     * 80 + co);
                ah[mi][1] = *(const uint32_t*)(pAh + (ra + 8) * 80 + co);
                ah[mi][2] = *(const uint32_t*)(pAh + (ra)     * 80 + co + 16);
                ah[mi][3] = *(const uint32_t*)(pAh + (ra + 8) * 80 + co + 16);
                al[mi][0] = *(const uint32_t*)(pAl + (ra)     * 80 + co);
                al[mi][1] = *(const uint32_t*)(pAl + (ra + 8) * 80 + co);
                al[mi][2] = *(const uint32_t*)(pAl + (ra)     * 80 + co + 16);
                al[mi][3] = *(const uint32_t*)(pAl + (ra + 8) * 80 + co + 16);
            }
#pragma unroll
            for (int ni = 0; ni < 8; ni++) {
                int rb = wn * 64 + ni * 8 + g;
                int co = (kb + t * 2) * 2;
                uint32_t bh[2], bl[2];
                bh[0] = *(const uint32_t*)(pBh + rb * 80 + co);
                bh[1] = *(const uint32_t*)(pBh + rb * 80 + co + 16);
                bl[0] = *(const uint32_t*)(pBl + rb * 80 + co);
                bl[1] = *(const uint32_t*)(pBl + rb * 80 + co + 16);
#pragma unroll
                for (int mi = 0; mi < 2; mi++) {
                    mma16816(acc[mi][ni], ah[mi], bh);
                    mma16816(acc[mi][ni], al[mi], bh);
                    mma16816(acc[mi][ni], ah[mi], bl);
                }
            }
        }
        __syncthreads();
        if (c + 2 < 32) load_chunk(c & 1, c + 2);
    }

#pragma unroll
    for (int mi = 0; mi < 2; mi++) {
        int m = m0 + wm * 32 + mi * 16 + g;
#pragma unroll
        for (int ni = 0; ni < 8; ni++) {
            int n = n0 + wn * 64 + ni * 8 + t * 2;
            float bx = __ldg(bias + n), by = __ldg(bias + n + 1);
            float2 v0 = {acc[mi][ni][0] + bx, acc[mi][ni][1] + by};
            float2 v1 = {acc[mi][ni][2] + bx, acc[mi][ni][3] + by};
            *(float2*)(zx + (size_t)m * kG + n) = v0;
            *(float2*)(zx + (size_t)(m + 8) * kG + n) = v1;
        }
    }
}

// ------------------------------ persistent transposed HMMA scan -------------
// 128 CTAs: CTA = dir*64 + g owns 8 units (32 gate rows of z^T).
#define SC_BSTRIDE 1040
#define SC_PLANE   (64 * SC_BSTRIDE)
#define SC_OFF_BH  65536
#define SC_OFF_BL  (SC_OFF_BH + SC_PLANE)
#define SCAN_SMEM  (SC_OFF_BL + SC_PLANE)

__global__ __launch_bounds__(256, 1) void scan_kernel(
    const float* __restrict__ Ur_f, const float* __restrict__ Ur_b,
    const int* __restrict__ enc,
    float* __restrict__ out2, float* __restrict__ h_final,
    float* __restrict__ c_final, int layer2) {
    extern __shared__ char dynsmem[];
    char* pA  = dynsmem;
    char* pBh = dynsmem + SC_OFF_BH;
    char* pBl = dynsmem + SC_OFF_BL;

    const int cta = blockIdx.x;
    const int d = cta >> 6;
    const int g = cta & 63;
    const int j0 = g * 8;
    const int tid = threadIdx.x;
    const int wid = tid >> 5, lane = tid & 31;
    const int fg = lane >> 2, ft = lane & 3;
    const int n0w = wid * 8;
    const int b0 = n0w + ft * 2, b1 = b0 + 1;
    const int spl = tid >> 7;
    const int srow = (tid >> 1) & 63;
    const int shalf = tid & 1;

    const float* __restrict__ Ur = d ? Ur_b : Ur_f;
    const float* __restrict__ ew = d ? g_embw1 : g_embw0;
    const float* __restrict__ zx = d ? g_zx1 : g_zx0;
    unsigned int* barp = &g_bar[layer2 * 2 + d];

    // -------- A (UrT slice) -> fragment-major smem, hi/lo, once ------------
    for (int i = tid; i < 4096; i += 256) {
        int ks = i >> 7, rest = i & 127;
        int mi = rest >> 6, pl = (rest >> 5) & 1, ln = rest & 31;
        int lfg = ln >> 2, lft = ln & 3;
        uint32_t regs[4];
#pragma unroll
        for (int r = 0; r < 4; ++r) {
            int m = mi * 16 + lfg + ((r & 1) << 3);
            int kk = ks * 16 + lft * 2 + ((r >> 1) << 3);
            int col = (m >> 3) * kU + j0 + (m & 7);
            float v0 = __ldg(Ur + (size_t)kk * kG + col);
            float v1 = __ldg(Ur + (size_t)(kk + 1) * kG + col);
            __nv_bfloat16 h0 = __float2bfloat16(v0);
            __nv_bfloat16 h1 = __float2bfloat16(v1);
            if (pl == 0) {
                regs[r] = pack_bf16x2(h0, h1);
            } else {
                __nv_bfloat16 l0 = __float2bfloat16(v0 - __bfloat162float(h0));
                __nv_bfloat16 l1 = __float2bfloat16(v1 - __bfloat162float(h1));
                regs[r] = pack_bf16x2(l0, l1);
            }
        }
        *(uint4*)(pA + (size_t)i * 16) = *(uint4*)regs;
    }
    __syncthreads();

    const uint32_t sdst = smem_u32(dynsmem) +
        (spl ? SC_OFF_BL : SC_OFF_BH) + srow * SC_BSTRIDE + shalf * 512;

    float hp[2] = {0.f, 0.f}, cp[2] = {0.f, 0.f};

    for (int s = 0; s < kT; ++s) {
        const int t = d ? (kT - 1 - s) : s;
        const int par = s & 1;
        const __nv_bfloat16* __restrict__ ihh = g_hh[layer2][d][par];
        const __nv_bfloat16* __restrict__ ihl = g_hl[layer2][d][par];
        __nv_bfloat16* __restrict__ ohh = g_hh[layer2][d][par ^ 1];
        __nv_bfloat16* __restrict__ ohl = g_hl[layer2][d][par ^ 1];

        // ---- stage B (h planes), single group, issued first ---------------
        const __nv_bfloat16* ssrc = (spl ? ihl : ihh) + srow * kU + shalf * 256;
#pragma unroll
        for (int c = 0; c < 32; ++c) cp16(sdst + c * 16, ssrc + c * 8);
        cp_commit();

        // ---- zx / token prefetch (independent LDGs overlap staging) -------
        const int tokA = __ldg(enc + b0 * kT + t);
        const int tokB = __ldg(enc + b1 * kT + t);
        float zr[2][4];
        if (!layer2) {
#pragma unroll
            for (int q = 0; q < 4; q++) {
                zr[0][q] = __ldg(ew + (size_t)tokA * kG + q * kU + j0 + fg);
                zr[1][q] = __ldg(ew + (size_t)tokB * kG + q * kU + j0 + fg);
            }
        } else {
#pragma unroll
            for (int q = 0; q < 4; q++) {
                zr[0][q] = __ldg(zx + ((size_t)t * kB + b0) * kG + q * kU + j0 + fg);
                zr[1][q] = __ldg(zx + ((size_t)t * kB + b1) * kG + q * kU + j0 + fg);
            }
        }

        cp_wait0();
        __syncthreads();

        // ---- HMMA: 3-pass hi/lo over all 32 ks -----------------------------
        float acc[2][4] = {{0.f, 0.f, 0.f, 0.f}, {0.f, 0.f, 0.f, 0.f}};
        const char* brh = pBh + (n0w + fg) * SC_BSTRIDE;
        const char* brl = pBl + (n0w + fg) * SC_BSTRIDE;
#pragma unroll 8
        for (int ks = 0; ks < 32; ++ks) {
            const int co = (ks * 16 + ft * 2) * 2;
            uint32_t bh[2], bl[2];
            bh[0] = *(const uint32_t*)(brh + co);
            bh[1] = *(const uint32_t*)(brh + co + 16);
            bl[0] = *(const uint32_t*)(brl + co);
            bl[1] = *(const uint32_t*)(brl + co + 16);
#pragma unroll
            for (int mi = 0; mi < 2; ++mi) {
                uint4 ah = *(const uint4*)(pA + ((ks * 4 + mi * 2) * 512) + lane * 16);
                uint4 al = *(const uint4*)(pA + ((ks * 4 + mi * 2 + 1) * 512) + lane * 16);
                mma16816(acc[mi], (const uint32_t*)&ah, bh);
                mma16816(acc[mi], (const uint32_t*)&al, bh);
                mma16816(acc[mi], (const uint32_t*)&ah, bl);
            }
        }

        // ---- LSTM epilogue: compute + h-plane stores -----------------------
        float hn_s[2], cn_s[2];
        __nv_bfloat16 bhi_s[2], blo_s[2];
#pragma unroll
        for (int c = 0; c < 2; ++c) {
            const int b = c ? b1 : b0;
            const int msk = c ? (tokB != 0) : (tokA != 0);
            float zi = acc[0][c]     + zr[c][0];
            float zf = acc[0][2 + c] + zr[c][1];
            float zg = acc[1][c]     + zr[c][2];
            float zo = acc[1][2 + c] + zr[c][3];
            float ii = sigmoidf_(zi), ff = sigmoidf_(zf);
            float gg = tanhf(zg), oo = sigmoidf_(zo);
            float cn = ff * cp[c] + ii * gg;
            float hn = oo * tanhf(cn);
            if (!msk) { hn = hp[c]; cn = cp[c]; }
            hp[c] = hn; cp[c] = cn;
            hn_s[c] = hn; cn_s[c] = cn;
            __nv_bfloat16 bhi = __float2bfloat16(hn);
            __nv_bfloat16 blo = __float2bfloat16(hn - __bfloat162float(bhi));
            bhi_s[c] = bhi; blo_s[c] = blo;
            ohh[b * kU + j0 + fg] = bhi;
            ohl[b * kU + j0 + fg] = blo;
        }

        if (s != kT - 1) {
            // arrive (release covers h-plane stores via syncthreads HB chain)
            __syncthreads();
            if (tid == 0) bar_arrive_release(barp);
            // out stores overlap other CTAs' arrival
#pragma unroll
            for (int c = 0; c < 2; ++c) {
                const int b = c ? b1 : b0;
                if (!layer2) {
                    size_t idx = ((size_t)t * kB + b) * kF + d * kU + j0 + fg;
                    g_ah[idx] = bhi_s[c];
                    g_al[idx] = blo_s[c];
                } else {
                    out2[((size_t)b * kT + t) * kF + d * kU + j0 + fg] = hn_s[c];
                }
            }
            if (tid == 0) {
                unsigned tgt = 64u * (unsigned)(s + 1);
                while (bar_poll_acquire(barp) < tgt) { }
            }
            __syncthreads();
        } else {
#pragma unroll
            for (int c = 0; c < 2; ++c) {
                const int b = c ? b1 : b0;
                if (!layer2) {
                    size_t idx = ((size_t)t * kB + b) * kF + d * kU + j0 + fg;
                    g_ah[idx] = bhi_s[c];
                    g_al[idx] = blo_s[c];
                } else {
                    out2[((size_t)b * kT + t) * kF + d * kU + j0 + fg] = hn_s[c];
                    h_final[b * kF + d * kU + j0 + fg] = hn_s[c];
                    c_final[b * kF + d * kU + j0 + fg] = cn_s[c];
                }
            }
        }
    }
}

// ------------------------------ launch --------------------------------------
extern "C" void kernel_launch(void* const* d_in, const int* in_sizes, int n_in,
                              void* d_out, int out_size) {
    const int*   enc = (const int*)d_in[0];
    const float* emb = (const float*)d_in[1];
    const float* W1f = (const float*)d_in[2];
    const float* U1f = (const float*)d_in[3];
    const float* b1f = (const float*)d_in[4];
    const float* W1b = (const float*)d_in[5];
    const float* U1b = (const float*)d_in[6];
    const float* b1b = (const float*)d_in[7];
    const float* W2f = (const float*)d_in[8];
    const float* U2f = (const float*)d_in[9];
    const float* b2f = (const float*)d_in[10];
    const float* W2b = (const float*)d_in[11];
    const float* U2b = (const float*)d_in[12];
    const float* b2b = (const float*)d_in[13];

    float* out  = (float*)d_out;
    float* out2 = out;                                   // [B,T,2U]
    float* h2   = out + (size_t)kB * kT * kF;
    float* c2   = h2 + (size_t)kB * kF;

    cudaFuncSetAttribute(scan_kernel, cudaFuncAttributeMaxDynamicSharedMemorySize,
                         SCAN_SMEM);
    cudaFuncSetAttribute(mma_gemm_kernel, cudaFuncAttributeMaxDynamicSharedMemorySize,
                         MM_SMEM);

    // embW = emb @ W1 + b1  (V=128 -> gather replaces layer-1 GEMM)
    gemm_f32<<<dim3(16, 1), 256>>>(emb, W1f, b1f, 0, kE);
    gemm_f32<<<dim3(16, 1), 256>>>(emb, W1b, b1b, 1, kE);

    // W2 transpose + bf16 hi/lo split
    wsplit_kernel<<<dim3(64, 32, 2), 256>>>(W2f, W2b);

    // zero h planes + barrier counters
    init_kernel<<<128, 256>>>();

    // layer-1 scan (transposed HMMA; emits bf16 hi/lo A operand)
    scan_kernel<<<128, 256, SCAN_SMEM>>>(U1f, U1b, enc,
                                         nullptr, nullptr, nullptr, 0);

    // layer-2 input projection: warp-mma bf16, 3-pass split, 2-stage pipeline
    mma_gemm_kernel<<<dim3(16, 128, 2), 256, MM_SMEM>>>(b2f, b2b);

    // layer-2 scan -> outputs
    scan_kernel<<<128, 256, SCAN_SMEM>>>(U2f, U2b, enc,
                                         out2, h2, c2, 1);
}